// round 9
// baseline (speedup 1.0000x reference)
#include <cuda_runtime.h>
#include <cstdint>

#define NQ 2048
#define NT 5
#define NB 32
#define NW 8                  // 8 warps, 256q per warp
#define TPB (NW * 32)         // 256 threads
#define NCAND 3125            // 5^5

static __device__ __forceinline__ unsigned long long umin64(unsigned long long a,
                                                            unsigned long long b) {
    return a < b ? a : b;
}
static __device__ __forceinline__ unsigned long long umax64(unsigned long long a,
                                                            unsigned long long b) {
    return a > b ? a : b;
}
#define CE(a, b) { unsigned long long _lo = umin64(a, b); b = umax64(a, b); a = _lo; }

// Merge sorted-ascending a[5] with DESCENDING brev[5]; keep 5 smallest sorted in a.
static __device__ __forceinline__ void merge_top5_rev(unsigned long long* a,
                                                      const unsigned long long* brev) {
    unsigned long long s0 = umin64(a[0], brev[0]);
    unsigned long long s1 = umin64(a[1], brev[1]);
    unsigned long long s2 = umin64(a[2], brev[2]);
    unsigned long long s3 = umin64(a[3], brev[3]);
    unsigned long long s4 = umin64(a[4], brev[4]);
    CE(s0, s1); CE(s3, s4); CE(s2, s4); CE(s2, s3); CE(s0, s3);
    CE(s0, s2); CE(s1, s4); CE(s1, s3); CE(s1, s2);
    a[0] = s0; a[1] = s1; a[2] = s2; a[3] = s3; a[4] = s4;
}

__global__ __launch_bounds__(TPB, 1)
void hungarian_match_kernel(const float* __restrict__ pred_regs,   // [32,2048,3]
                            const float* __restrict__ tgt,         // [160,3]
                            float* __restrict__ out)               // [2,32,5] f32
{
    __shared__ unsigned long long sm_lists[NW][NT][NT];   // 1.6 KB
    __shared__ int   sel_idx[NT][NT];
    __shared__ float sel_val[NT][NT];
    __shared__ unsigned long long red[NW];

    const int b    = blockIdx.x;
    const int tid  = threadIdx.x;
    const int w    = tid >> 5;
    const int lane = tid & 31;

    // ---- all 5 targets into registers (broadcast loads) ----
    float tgx[NT], tgy[NT], tgz[NT];
    #pragma unroll
    for (int t = 0; t < NT; t++) {
        tgx[t] = __ldg(&tgt[b * NT * 3 + t * 3 + 0]);
        tgy[t] = __ldg(&tgt[b * NT * 3 + t * 3 + 1]);
        tgz[t] = __ldg(&tgt[b * NT * 3 + t * 3 + 2]);
    }

    // ---- front-load this lane's 8 queries: 6 independent LDG.128 ----
    const float* pr = pred_regs + (size_t)b * NQ * 3;
    const int q0 = w * 256 + lane * 8;                 // q0*3 % 4 == 0
    const float4* p4 = (const float4*)(pr + (size_t)q0 * 3);
    float4 v0 = __ldg(&p4[0]);
    float4 v1 = __ldg(&p4[1]);
    float4 v2 = __ldg(&p4[2]);
    float4 v3 = __ldg(&p4[3]);
    float4 v4 = __ldg(&p4[4]);
    float4 v5 = __ldg(&p4[5]);

    float px[8], py[8], pz[8];
    px[0] = v0.x; py[0] = v0.y; pz[0] = v0.z;
    px[1] = v0.w; py[1] = v1.x; pz[1] = v1.y;
    px[2] = v1.z; py[2] = v1.w; pz[2] = v2.x;
    px[3] = v2.y; py[3] = v2.z; pz[3] = v2.w;
    px[4] = v3.x; py[4] = v3.y; pz[4] = v3.z;
    px[5] = v3.w; py[5] = v4.x; pz[5] = v4.y;
    px[6] = v4.z; py[6] = v4.w; pz[6] = v5.x;
    px[7] = v5.y; py[7] = v5.z; pz[7] = v5.w;

    // ---- per-lane top-5 for ALL 5 targets from register data ----
    // key = float_bits(cost)<<32 | q ; costs >= 1 > 0 so uint order == float
    // order; unique keys reproduce jax.lax.top_k's stable tie-break exactly.
    unsigned long long m[NT][NT];
    #pragma unroll
    for (int t = 0; t < NT; t++)
        #pragma unroll
        for (int k = 0; k < NT; k++) m[t][k] = ~0ULL;

    #pragma unroll
    for (int e = 0; e < 8; e++) {
        #pragma unroll
        for (int t = 0; t < NT; t++) {
            float a0 = fabsf(__fsub_rn(px[e], tgx[t]));
            float a1 = fabsf(__fsub_rn(py[e], tgy[t]));
            float a2 = fabsf(__fsub_rn(pz[e], tgz[t]));
            float c  = __fadd_rn(__fadd_rn(__fadd_rn(a0, a1), a2), 1.0f);
            unsigned long long key =
                ((unsigned long long)__float_as_uint(c) << 32) |
                (unsigned int)(q0 + e);
            if (key < m[t][4]) {
                m[t][4] = key;
                unsigned long long tmp;
                if (m[t][4] < m[t][3]) { tmp = m[t][3]; m[t][3] = m[t][4]; m[t][4] = tmp; }
                if (m[t][3] < m[t][2]) { tmp = m[t][2]; m[t][2] = m[t][3]; m[t][3] = tmp; }
                if (m[t][2] < m[t][1]) { tmp = m[t][1]; m[t][1] = m[t][2]; m[t][2] = tmp; }
                if (m[t][1] < m[t][0]) { tmp = m[t][0]; m[t][0] = m[t][1]; m[t][1] = tmp; }
            }
        }
    }

    // ---- 5 independent warp bitonic merges (ILP across targets) ----
    #pragma unroll
    for (int off = 16; off > 0; off >>= 1) {
        #pragma unroll
        for (int t = 0; t < NT; t++) {
            unsigned long long o[NT];
            #pragma unroll
            for (int k = 0; k < NT; k++)
                o[NT - 1 - k] = __shfl_xor_sync(0xffffffffu, m[t][k], off);
            merge_top5_rev(m[t], o);
        }
    }
    if (lane == 0) {
        #pragma unroll
        for (int t = 0; t < NT; t++)
            #pragma unroll
            for (int k = 0; k < NT; k++) sm_lists[w][t][k] = m[t][k];
    }
    __syncthreads();

    // ---- phase 2: warp t (t<5) merges the 8 warp-lists for target t ----
    if (w < NT) {
        unsigned long long A[NT];
        #pragma unroll
        for (int k = 0; k < NT; k++)
            A[k] = (lane < NW) ? sm_lists[lane][w][k] : ~0ULL;
        #pragma unroll
        for (int off = 4; off > 0; off >>= 1) {     // lanes 0..7 tree
            unsigned long long o[NT];
            #pragma unroll
            for (int k = 0; k < NT; k++)
                o[NT - 1 - k] = __shfl_xor_sync(0xffffffffu, A[k], off);
            merge_top5_rev(A, o);
        }
        if (lane == 0) {
            #pragma unroll
            for (int k = 0; k < NT; k++) {
                sel_idx[w][k] = (int)(unsigned int)A[k];
                sel_val[w][k] = __uint_as_float((unsigned int)(A[k] >> 32));
            }
        }
    }
    __syncthreads();

    // ---- 3125 tuples over 256 threads; argmin of f32 sum, first-occurrence ----
    unsigned long long best = ~0ULL;
    for (int n = tid; n < NCAND; n += TPB) {
        int r  = n;
        int d0 = r / 625;  r -= d0 * 625;
        int d1 = r / 125;  r -= d1 * 125;
        int d2 = r / 25;   r -= d2 * 25;
        int d3 = r / 5;
        int d4 = r - d3 * 5;
        int q0e = sel_idx[0][d0], q1e = sel_idx[1][d1], q2e = sel_idx[2][d2],
            q3e = sel_idx[3][d3], q4e = sel_idx[4][d4];
        bool valid = (q0e != q1e) && (q0e != q2e) && (q0e != q3e) && (q0e != q4e) &&
                     (q1e != q2e) && (q1e != q3e) && (q1e != q4e) &&
                     (q2e != q3e) && (q2e != q4e) && (q3e != q4e);
        if (valid) {
            float tot = __fadd_rn(
                            __fadd_rn(
                                __fadd_rn(
                                    __fadd_rn(sel_val[0][d0], sel_val[1][d1]),
                                    sel_val[2][d2]),
                                sel_val[3][d3]),
                            sel_val[4][d4]);
            unsigned long long key =
                ((unsigned long long)__float_as_uint(tot) << 32) | (unsigned int)n;
            best = umin64(best, key);
        }
    }
    #pragma unroll
    for (int s = 16; s > 0; s >>= 1)
        best = umin64(best, __shfl_xor_sync(0xffffffffu, best, s));
    if (lane == 0) red[w] = best;
    __syncthreads();

    // ---- warp 0: parallel final reduce; lane 0 decodes + writes ----
    if (w == 0) {
        unsigned long long bb = (lane < NW) ? red[lane] : ~0ULL;
        #pragma unroll
        for (int s = 4; s > 0; s >>= 1)
            bb = umin64(bb, __shfl_xor_sync(0xffffffffu, bb, s));
        if (lane == 0) {
            int n = (int)(unsigned int)bb;
            int d[NT];
            d[0] = n / 625; n %= 625;
            d[1] = n / 125; n %= 125;
            d[2] = n / 25;  n %= 25;
            d[3] = n / 5;
            d[4] = n % 5;
            int rows[NT], cols[NT];
            #pragma unroll
            for (int j = 0; j < NT; j++) { rows[j] = sel_idx[j][d[j]]; cols[j] = j; }
            #pragma unroll
            for (int i = 1; i < NT; i++) {     // stable insertion sort by rows
                int rv = rows[i], cv = cols[i], j = i - 1;
                while (j >= 0 && rows[j] > rv) {
                    rows[j + 1] = rows[j]; cols[j + 1] = cols[j]; j--;
                }
                rows[j + 1] = rv; cols[j + 1] = cv;
            }
            #pragma unroll
            for (int j = 0; j < NT; j++) {
                out[b * NT + j]           = (float)rows[j];   // rows [32,5]
                out[NB * NT + b * NT + j] = (float)cols[j];   // cols [32,5]
            }
        }
    }
}

extern "C" void kernel_launch(void* const* d_in, const int* in_sizes, int n_in,
                              void* d_out, int out_size) {
    // Bind by size (confirmed working): pred_regs = 196608 f32, tgt = 480 f32.
    int pr_i = -1, tg_i = -1, max_i = 0;
    for (int i = 0; i < n_in; i++) {
        if (in_sizes[i] == 196608 || in_sizes[i] == 786432) pr_i = i;
        if (in_sizes[i] == 480    || in_sizes[i] == 1920)   tg_i = i;
        if (in_sizes[i] > in_sizes[max_i]) max_i = i;
    }
    if (pr_i < 0) pr_i = max_i;
    if (tg_i < 0) tg_i = (n_in > 3) ? 3 : n_in - 1;

    const float* pred_regs = (const float*)d_in[pr_i];
    const float* tgt       = (const float*)d_in[tg_i];
    float* out = (float*)d_out;
    hungarian_match_kernel<<<NB, TPB>>>(pred_regs, tgt, out);
}

// round 10
// speedup vs baseline: 1.3233x; 1.3233x over previous
#include <cuda_runtime.h>
#include <cstdint>

#define NQ 2048
#define NT 5
#define NB 32
#define NCAND 3125            // 5^5

// Cross-kernel scratch (device global: allocation-free).
__device__ unsigned long long g_sel[NB][NT][NT];

static __device__ __forceinline__ unsigned long long umin64(unsigned long long a,
                                                            unsigned long long b) {
    return a < b ? a : b;
}
static __device__ __forceinline__ unsigned long long umax64(unsigned long long a,
                                                            unsigned long long b) {
    return a > b ? a : b;
}
#define CE(a, b) { unsigned long long _lo = umin64(a, b); b = umax64(a, b); a = _lo; }

// Merge sorted-ascending a[5] with DESCENDING brev[5]; keep 5 smallest sorted in a.
static __device__ __forceinline__ void merge_top5_rev(unsigned long long* a,
                                                      const unsigned long long* brev) {
    unsigned long long s0 = umin64(a[0], brev[0]);
    unsigned long long s1 = umin64(a[1], brev[1]);
    unsigned long long s2 = umin64(a[2], brev[2]);
    unsigned long long s3 = umin64(a[3], brev[3]);
    unsigned long long s4 = umin64(a[4], brev[4]);
    CE(s0, s1); CE(s3, s4); CE(s2, s4); CE(s2, s3); CE(s0, s3);
    CE(s0, s2); CE(s1, s4); CE(s1, s3); CE(s1, s2);
    a[0] = s0; a[1] = s1; a[2] = s2; a[3] = s3; a[4] = s4;
}

// ============ Kernel A: per-(batch,target) top-5 ============
// grid = (NT, NB), block = 256. Each CTA scans 2048 queries for one target.
__global__ __launch_bounds__(256, 1)
void topk_kernel(const float* __restrict__ pred_regs,   // [32,2048,3]
                 const float* __restrict__ tgt)         // [160,3]
{
    __shared__ unsigned long long sm_lists[8][NT];

    const int t    = blockIdx.x;
    const int b    = blockIdx.y;
    const int tid  = threadIdx.x;
    const int w    = tid >> 5;
    const int lane = tid & 31;

    const float t0f = __ldg(&tgt[b * NT * 3 + t * 3 + 0]);
    const float t1f = __ldg(&tgt[b * NT * 3 + t * 3 + 1]);
    const float t2f = __ldg(&tgt[b * NT * 3 + t * 3 + 2]);

    // ---- front-load this thread's 8 queries: 6 independent LDG.128 ----
    const float* pr = pred_regs + (size_t)b * NQ * 3;
    const int q0 = tid * 8;                            // q0*3 % 4 == 0
    const float4* p4 = (const float4*)(pr + (size_t)q0 * 3);
    float4 v0 = __ldg(&p4[0]);
    float4 v1 = __ldg(&p4[1]);
    float4 v2 = __ldg(&p4[2]);
    float4 v3 = __ldg(&p4[3]);
    float4 v4 = __ldg(&p4[4]);
    float4 v5 = __ldg(&p4[5]);

    float px[8], py[8], pz[8];
    px[0] = v0.x; py[0] = v0.y; pz[0] = v0.z;
    px[1] = v0.w; py[1] = v1.x; pz[1] = v1.y;
    px[2] = v1.z; py[2] = v1.w; pz[2] = v2.x;
    px[3] = v2.y; py[3] = v2.z; pz[3] = v2.w;
    px[4] = v3.x; py[4] = v3.y; pz[4] = v3.z;
    px[5] = v3.w; py[5] = v4.x; pz[5] = v4.y;
    px[6] = v4.z; py[6] = v4.w; pz[6] = v5.x;
    px[7] = v5.y; py[7] = v5.z; pz[7] = v5.w;

    // ---- per-lane top-5 (bit-exact XLA cost order) ----
    // key = float_bits(cost)<<32 | q ; costs >= 1 > 0 so uint order == float
    // order; unique keys reproduce jax.lax.top_k's stable tie-break exactly.
    unsigned long long m[NT] = {~0ULL, ~0ULL, ~0ULL, ~0ULL, ~0ULL};
    #pragma unroll
    for (int e = 0; e < 8; e++) {
        float a0 = fabsf(__fsub_rn(px[e], t0f));
        float a1 = fabsf(__fsub_rn(py[e], t1f));
        float a2 = fabsf(__fsub_rn(pz[e], t2f));
        float c  = __fadd_rn(__fadd_rn(__fadd_rn(a0, a1), a2), 1.0f);
        unsigned long long key =
            ((unsigned long long)__float_as_uint(c) << 32) | (unsigned int)(q0 + e);
        if (key < m[4]) {
            m[4] = key;
            unsigned long long tmp;
            if (m[4] < m[3]) { tmp = m[3]; m[3] = m[4]; m[4] = tmp; }
            if (m[3] < m[2]) { tmp = m[2]; m[2] = m[3]; m[3] = tmp; }
            if (m[2] < m[1]) { tmp = m[1]; m[1] = m[2]; m[2] = tmp; }
            if (m[1] < m[0]) { tmp = m[0]; m[0] = m[1]; m[1] = tmp; }
        }
    }

    // ---- warp bitonic merge: 5 levels ----
    #pragma unroll
    for (int off = 16; off > 0; off >>= 1) {
        unsigned long long o[NT];
        #pragma unroll
        for (int k = 0; k < NT; k++)
            o[NT - 1 - k] = __shfl_xor_sync(0xffffffffu, m[k], off);
        merge_top5_rev(m, o);
    }
    if (lane == 0) {
        #pragma unroll
        for (int k = 0; k < NT; k++) sm_lists[w][k] = m[k];
    }
    __syncthreads();

    // ---- warp 0: cross-warp merge (8 lists, 3 shuffle levels); write ----
    if (w == 0) {
        unsigned long long A[NT];
        #pragma unroll
        for (int k = 0; k < NT; k++)
            A[k] = (lane < 8) ? sm_lists[lane][k] : ~0ULL;
        #pragma unroll
        for (int off = 4; off > 0; off >>= 1) {
            unsigned long long o[NT];
            #pragma unroll
            for (int k = 0; k < NT; k++)
                o[NT - 1 - k] = __shfl_xor_sync(0xffffffffu, A[k], off);
            merge_top5_rev(A, o);
        }
        if (lane == 0) {
            #pragma unroll
            for (int k = 0; k < NT; k++) g_sel[b][t][k] = A[k];
        }
    }
}

// ============ Kernel B: enumeration + output ============
// grid = NB, block = 640.
__global__ __launch_bounds__(640, 1)
void assign_kernel(float* __restrict__ out)             // [2,32,5] f32
{
    __shared__ int   sel_idx[NT][NT];
    __shared__ float sel_val[NT][NT];
    __shared__ unsigned long long red[20];

    const int b    = blockIdx.x;
    const int tid  = threadIdx.x;
    const int w    = tid >> 5;
    const int lane = tid & 31;

    if (tid < NT * NT) {
        unsigned long long v = g_sel[b][tid / NT][tid % NT];
        sel_idx[tid / NT][tid % NT] = (int)(unsigned int)v;
        sel_val[tid / NT][tid % NT] = __uint_as_float((unsigned int)(v >> 32));
    }
    __syncthreads();

    // ---- 3125 tuples over 640 threads; argmin of f32 sum, first-occurrence ----
    unsigned long long best = ~0ULL;
    #pragma unroll
    for (int it = 0; it < 5; it++) {
        int n = tid + it * 640;
        if (n < NCAND) {
            int r  = n;
            int d0 = r / 625;  r -= d0 * 625;
            int d1 = r / 125;  r -= d1 * 125;
            int d2 = r / 25;   r -= d2 * 25;
            int d3 = r / 5;
            int d4 = r - d3 * 5;
            int q0 = sel_idx[0][d0], q1 = sel_idx[1][d1], q2 = sel_idx[2][d2],
                q3 = sel_idx[3][d3], q4 = sel_idx[4][d4];
            bool valid = (q0 != q1) && (q0 != q2) && (q0 != q3) && (q0 != q4) &&
                         (q1 != q2) && (q1 != q3) && (q1 != q4) &&
                         (q2 != q3) && (q2 != q4) && (q3 != q4);
            if (valid) {
                float tot = __fadd_rn(
                                __fadd_rn(
                                    __fadd_rn(
                                        __fadd_rn(sel_val[0][d0], sel_val[1][d1]),
                                        sel_val[2][d2]),
                                    sel_val[3][d3]),
                                sel_val[4][d4]);
                unsigned long long key =
                    ((unsigned long long)__float_as_uint(tot) << 32) |
                    (unsigned int)n;
                best = umin64(best, key);
            }
        }
    }
    #pragma unroll
    for (int s = 16; s > 0; s >>= 1)
        best = umin64(best, __shfl_xor_sync(0xffffffffu, best, s));
    if (lane == 0) red[w] = best;
    __syncthreads();

    if (w == 0) {
        unsigned long long bb = (lane < 20) ? red[lane] : ~0ULL;
        #pragma unroll
        for (int s = 16; s > 0; s >>= 1)
            bb = umin64(bb, __shfl_xor_sync(0xffffffffu, bb, s));
        if (lane == 0) {
            int n = (int)(unsigned int)bb;
            int d[NT];
            d[0] = n / 625; n %= 625;
            d[1] = n / 125; n %= 125;
            d[2] = n / 25;  n %= 25;
            d[3] = n / 5;
            d[4] = n % 5;
            int rows[NT], cols[NT];
            #pragma unroll
            for (int j = 0; j < NT; j++) { rows[j] = sel_idx[j][d[j]]; cols[j] = j; }
            #pragma unroll
            for (int i = 1; i < NT; i++) {     // stable insertion sort by rows
                int rv = rows[i], cv = cols[i], j = i - 1;
                while (j >= 0 && rows[j] > rv) {
                    rows[j + 1] = rows[j]; cols[j + 1] = cols[j]; j--;
                }
                rows[j + 1] = rv; cols[j + 1] = cv;
            }
            #pragma unroll
            for (int j = 0; j < NT; j++) {
                out[b * NT + j]           = (float)rows[j];   // rows [32,5]
                out[NB * NT + b * NT + j] = (float)cols[j];   // cols [32,5]
            }
        }
    }
}

extern "C" void kernel_launch(void* const* d_in, const int* in_sizes, int n_in,
                              void* d_out, int out_size) {
    // Bind by size (confirmed working): pred_regs = 196608 f32, tgt = 480 f32.
    int pr_i = -1, tg_i = -1, max_i = 0;
    for (int i = 0; i < n_in; i++) {
        if (in_sizes[i] == 196608 || in_sizes[i] == 786432) pr_i = i;
        if (in_sizes[i] == 480    || in_sizes[i] == 1920)   tg_i = i;
        if (in_sizes[i] > in_sizes[max_i]) max_i = i;
    }
    if (pr_i < 0) pr_i = max_i;
    if (tg_i < 0) tg_i = (n_in > 3) ? 3 : n_in - 1;

    const float* pred_regs = (const float*)d_in[pr_i];
    const float* tgt       = (const float*)d_in[tg_i];
    float* out = (float*)d_out;

    dim3 gridA(NT, NB);
    topk_kernel<<<gridA, 256>>>(pred_regs, tgt);
    assign_kernel<<<NB, 640>>>(out);
}